// round 12
// baseline (speedup 1.0000x reference)
#include <cuda_runtime.h>
#include <cuda_fp16.h>
#include <cstdint>
#include <math.h>

#define DEV_INLINE __device__ __forceinline__

// Problem dims (fixed by the dataset)
constexpr int B_ = 128, T_ = 512, F_ = 512, M_ = 512;
constexpr float LN_EPS = 1e-5f;

// GEMM tiling (R7, verified 124.5us): CTA 128x128x64; 8 warps of 32x64; fp16 mma k16, f32 acc
constexpr int BM = 128, BN = 128, BK = 64;
constexpr int NKC = T_ / BK;     // 8 k-chunks
constexpr int THREADS = 256;
constexpr int NSTAGE = 3;

constexpr int A_STAGE_B = BM * BK * 2;            // 16384 B
constexpr int B_STAGE_B = BN * BK * 2;            // 16384 B
constexpr int STAGE_B   = A_STAGE_B + B_STAGE_B;  // 32 KB
constexpr int SMEM_BYTES = NSTAGE * STAGE_B;      // 96 KB

// Device scratch (no allocation allowed)
__device__ uint4 g_WfragH[32 * 16 * 2 * 32];           // 512KB: [m16][kc16][kstep2][lane]
__device__ uint4 g_BfragH[(size_t)B_ * 4 * 16 * 512];  // 64MB: [b][ft][kc16][np][kstep2][lane]

// ---------------- helpers ----------------
DEV_INLINE uint32_t smem_u32(const void* p) {
    uint32_t a;
    asm("{ .reg .u64 t; cvta.to.shared.u64 t, %1; cvt.u32.u64 %0, t; }"
        : "=r"(a) : "l"(p));
    return a;
}

DEV_INLINE uint32_t h2pack(float a, float b) {
    __half2 h = __floats2half2_rn(a, b);
    return *reinterpret_cast<uint32_t*>(&h);
}

DEV_INLINE void cp_async16(uint32_t dst_smem, const void* src) {
    asm volatile(
        "{\n\t.reg .u64 g;\n\tcvta.to.global.u64 g, %1;\n\t"
        "cp.async.cg.shared.global [%0], [g], 16;\n\t}"
        :: "r"(dst_smem), "l"(src));
}
DEV_INLINE void cp_commit() { asm volatile("cp.async.commit_group;"); }
template <int N> DEV_INLINE void cp_wait() {
    asm volatile("cp.async.wait_group %0;" :: "n"(N));
}

// m16n8k16 fp16 mma, fp32 accumulate (the sm_103a-optimal legacy path)
DEV_INLINE void mma_f16(float* c, const uint32_t* a, uint32_t b0, uint32_t b1) {
    asm volatile(
        "mma.sync.aligned.m16n8k16.row.col.f32.f16.f16.f32 "
        "{%0,%1,%2,%3}, {%4,%5,%6,%7}, {%8,%9}, {%0,%1,%2,%3};"
        : "+f"(c[0]), "+f"(c[1]), "+f"(c[2]), "+f"(c[3])
        : "r"(a[0]), "r"(a[1]), "r"(a[2]), "r"(a[3]), "r"(b0), "r"(b1));
}

DEV_INLINE float gelu_exact(float v) {
    return 0.5f * v * (1.0f + erff(v * 0.70710678118654752f));
}

// ---------------- kernel 1: fused LN-stats + normalize + fp16 B-frag pack, + W pack --
// Blocks 0..511: (b, ft) slabs. Blocks 512..639: pack W.
__global__ __launch_bounds__(256) void prep_kernel(const float* __restrict__ x,
                                                   const float* __restrict__ gamma,
                                                   const float* __restrict__ beta,
                                                   const float* __restrict__ W) {
    const int tid = threadIdx.x;

    if (blockIdx.x >= 512) {                       // ---- pack W -> fp16 A-frag order
        int lin = (blockIdx.x - 512) * 256 + tid;  // 32768 uint4s
        int lane = lin & 31;
        int kstep = (lin >> 5) & 1;
        int kc = (lin >> 6) & 15;
        int m16 = lin >> 10;
        int g = lane >> 2, tig = lane & 3;
        int mr = m16 * 16 + g;
        int tc = kc * 32 + kstep * 16 + 2 * tig;
        const float* w0 = W + (size_t)mr * T_ + tc;
        const float* w8 = W + (size_t)(mr + 8) * T_ + tc;
        uint4 v;
        v.x = h2pack(w0[0], w0[1]);
        v.y = h2pack(w8[0], w8[1]);
        v.z = h2pack(w0[8], w0[9]);
        v.w = h2pack(w8[8], w8[9]);
        g_WfragH[lin] = v;
        return;
    }

    // ---- (b, ft) slab: two-pass LN + pack ----
    __shared__ float s[32][132];                   // pass-2 tile
    __shared__ float s_mu[128], s_rs[128];
    __shared__ float s_red[512];                   // reduction scratch (s,ss interleaved halves)
    __shared__ float s_g[T_], s_b[T_];

    const int b = blockIdx.x >> 2;
    const int ft = blockIdx.x & 3;

    // stage gamma/beta
#pragma unroll
    for (int r = 0; r < 2; r++) {
        int i = tid + r * 256;
        s_g[i] = gamma[i];
        s_b[i] = beta[i];
    }

    // pass 1: per-f sum/sumsq over T (2 threads per f: t-halves)
    {
        const int f = tid & 127;
        const int th = tid >> 7;                   // 0 or 1
        const float* xp = x + ((size_t)b * T_ + th) * F_ + ft * 128 + f;
        float sm = 0.f, sq = 0.f;
#pragma unroll 8
        for (int t = 0; t < 256; t++) {
            float v = xp[(size_t)(2 * t) * F_];
            sm += v;
            sq += v * v;
        }
        s_red[tid] = sm;
        s_red[tid + 256] = sq;
    }
    __syncthreads();
    if (tid < 128) {
        float sm = s_red[tid] + s_red[tid + 128];
        float sq = s_red[tid + 256] + s_red[tid + 384];
        float mean = sm * (1.0f / T_);
        float var = sq * (1.0f / T_) - mean * mean;
        s_mu[tid] = mean;
        s_rs[tid] = rsqrtf(fmaxf(var, 0.0f) + LN_EPS);
    }
    __syncthreads();

    // pass 2: per-kc normalize + transpose + fp16 frag pack (x re-read hits L2)
    uint4* dst_base = g_BfragH + (((size_t)b * 4 + ft) * 16) * 512;
    for (int kc = 0; kc < 16; kc++) {
#pragma unroll
        for (int r = 0; r < 4; r++) {
            int i4 = tid + r * 256;
            int tl = i4 >> 5;
            int f4 = (i4 & 31) << 2;
            int gt = kc * 32 + tl;
            float4 v = *reinterpret_cast<const float4*>(
                x + ((size_t)b * T_ + gt) * F_ + ft * 128 + f4);
            float ga = s_g[gt], be = s_b[gt];
            s[tl][f4 + 0] = (v.x - s_mu[f4 + 0]) * s_rs[f4 + 0] * ga + be;
            s[tl][f4 + 1] = (v.y - s_mu[f4 + 1]) * s_rs[f4 + 1] * ga + be;
            s[tl][f4 + 2] = (v.z - s_mu[f4 + 2]) * s_rs[f4 + 2] * ga + be;
            s[tl][f4 + 3] = (v.w - s_mu[f4 + 3]) * s_rs[f4 + 3] * ga + be;
        }
        __syncthreads();

        uint4* dst = dst_base + (size_t)kc * 512;
#pragma unroll
        for (int r = 0; r < 2; r++) {
            int o = tid + r * 256;                 // 512 uint4s
            int np = o >> 6;
            int rem = o & 63;
            int kstep = rem >> 5;
            int lane = rem & 31;
            int g = lane >> 2, tig = lane & 3;
            int t0 = kstep * 16 + 2 * tig;
            int f0 = np * 16 + g;
            uint4 v;
            v.x = h2pack(s[t0][f0],     s[t0 + 1][f0]);
            v.y = h2pack(s[t0 + 8][f0], s[t0 + 9][f0]);
            v.z = h2pack(s[t0][f0 + 8],     s[t0 + 1][f0 + 8]);
            v.w = h2pack(s[t0 + 8][f0 + 8], s[t0 + 9][f0 + 8]);
            dst[o] = v;
        }
        __syncthreads();                           // s reused next kc
    }
}

// ---------------- kernel 2: fp16 GEMM (f32 acc) + bias + GELU + residual (R7) -------
// BK=64: smem A = [m16l (8)][ks (4)][lane], B = [np (8)][ks (4)][lane] (uint4 units)
__global__ __launch_bounds__(THREADS, 2)
void timemix_gemm_kernel(const float* __restrict__ x,
                         const float* __restrict__ bvec,
                         float* __restrict__ out) {
    extern __shared__ char smem[];
    const int tid = threadIdx.x;
    const int wid = tid >> 5, lane = tid & 31;
    const int wm = wid & 3, wn = wid >> 2;          // 4 x 2 warps (32m x 64f)
    const int bm = blockIdx.x;                      // 0..3
    const int ft = blockIdx.y;                      // 0..3
    const int b = blockIdx.z;

    const uint32_t smem_base = smem_u32(smem);
    const uint4* Bsrc_base = g_BfragH + (((size_t)b * 4 + ft) * 16) * 512;

    auto load_stage = [&](int kc8) {
        uint32_t sA = smem_base + (kc8 % NSTAGE) * STAGE_B;
        uint32_t sB = sA + A_STAGE_B;
#pragma unroll
        for (int r = 0; r < 4; r++) {               // A: 1024 uint4s
            int i = tid + r * 256;
            int m16l = i >> 7;
            int off = i & 127;                      // ks*32 + lane
            const uint4* src = g_WfragH + (((size_t)(bm * 8 + m16l) * 32) + kc8 * 4) * 32 + off;
            cp_async16(sA + i * 16, src);
        }
#pragma unroll
        for (int r = 0; r < 4; r++) {               // B: 1024 uint4s
            int i = tid + r * 256;
            int np = i >> 7;
            int rem = i & 127;
            int ks = rem >> 5;
            int ln = rem & 31;
            const uint4* src = Bsrc_base + (size_t)(2 * kc8 + (ks >> 1)) * 512
                               + np * 64 + (ks & 1) * 32 + ln;
            cp_async16(sB + i * 16, src);
        }
        cp_commit();
    };

    float acc[2][8][4];
#pragma unroll
    for (int i = 0; i < 2; i++)
#pragma unroll
        for (int j = 0; j < 8; j++)
#pragma unroll
            for (int r = 0; r < 4; r++) acc[i][j][r] = 0.0f;

    load_stage(0);
    load_stage(1);

    for (int kc = 0; kc < NKC; kc++) {
        if (kc + 1 < NKC) cp_wait<1>(); else cp_wait<0>();
        __syncthreads();

        const uint4* sA = reinterpret_cast<const uint4*>(smem + (kc % NSTAGE) * STAGE_B);
        const uint4* sB = reinterpret_cast<const uint4*>(
            smem + (kc % NSTAGE) * STAGE_B + A_STAGE_B);

#pragma unroll
        for (int kstep = 0; kstep < 4; kstep++) {
            uint32_t a[2][4];
#pragma unroll
            for (int i = 0; i < 2; i++) {
                uint4 v = sA[((wm * 2 + i) * 4 + kstep) * 32 + lane];
                a[i][0] = v.x; a[i][1] = v.y; a[i][2] = v.z; a[i][3] = v.w;
            }
            uint4 bf[4];
#pragma unroll
            for (int jp = 0; jp < 4; jp++)
                bf[jp] = sB[((wn * 4 + jp) * 4 + kstep) * 32 + lane];
#pragma unroll
            for (int i = 0; i < 2; i++)
#pragma unroll
                for (int jp = 0; jp < 4; jp++) {
                    mma_f16(acc[i][2 * jp + 0], a[i], bf[jp].x, bf[jp].y);
                    mma_f16(acc[i][2 * jp + 1], a[i], bf[jp].z, bf[jp].w);
                }
        }

        if (kc + 2 < NKC) load_stage(kc + 2);
    }

    // ---- epilogue: bias + exact GELU + residual ----
    const int g = lane >> 2, tig = lane & 3;
    const int m_warp = bm * 128 + wm * 32;
    const int f_warp = ft * 128 + wn * 64;
#pragma unroll
    for (int i = 0; i < 2; i++) {
#pragma unroll
        for (int h = 0; h < 2; h++) {
            int m = m_warp + i * 16 + g + 8 * h;
            float bv = bvec[m];
            const float* xr = x + ((size_t)b * M_ + m) * F_ + f_warp;
            float* yr = out + ((size_t)b * M_ + m) * F_ + f_warp;
#pragma unroll
            for (int j = 0; j < 8; j++) {
                int fo = j * 8 + tig * 2;
                float2 xv = *reinterpret_cast<const float2*>(xr + fo);
                float2 o;
                o.x = gelu_exact(acc[i][j][2 * h + 0] + bv) + xv.x;
                o.y = gelu_exact(acc[i][j][2 * h + 1] + bv) + xv.y;
                *reinterpret_cast<float2*>(yr + fo) = o;
            }
        }
    }
}

// ---------------- launch ----------------
extern "C" void kernel_launch(void* const* d_in, const int* in_sizes, int n_in,
                              void* d_out, int out_size) {
    const float* x     = (const float*)d_in[0];
    const float* gamma = (const float*)d_in[1];
    const float* beta  = (const float*)d_in[2];
    const float* W     = (const float*)d_in[3];
    const float* bvec  = (const float*)d_in[4];
    float* out = (float*)d_out;

    cudaFuncSetAttribute(timemix_gemm_kernel,
                         cudaFuncAttributeMaxDynamicSharedMemorySize, SMEM_BYTES);

    prep_kernel<<<512 + 128, 256>>>(x, gamma, beta, W);
    {
        dim3 grid(M_ / BM, F_ / BN, B_);   // (4, 4, 128)
        timemix_gemm_kernel<<<grid, THREADS, SMEM_BYTES>>>(x, bvec, out);
    }
}

// round 13
// speedup vs baseline: 1.0815x; 1.0815x over previous
#include <cuda_runtime.h>
#include <cuda_fp16.h>
#include <cstdint>
#include <math.h>

#define DEV_INLINE __device__ __forceinline__

// Problem dims (fixed by the dataset)
constexpr int B_ = 128, T_ = 512, F_ = 512, M_ = 512;
constexpr float LN_EPS = 1e-5f;

// GEMM tiling: CTA 128x128x64; 8 warps of 32x64; fp16 mma k16, f32 acc.
// A fragments come straight from L2 via LDG (no smem); B via cp.async pipeline.
constexpr int BM = 128, BN = 128, BK = 64;
constexpr int NKC = T_ / BK;     // 8 k-chunks
constexpr int THREADS = 256;
constexpr int NSTAGE = 4;

constexpr int B_STAGE_B = BN * BK * 2;            // 16384 B (B-frags only)
constexpr int SMEM_BYTES = NSTAGE * B_STAGE_B;    // 64 KB

// Device scratch (no allocation allowed)
__device__ float g_s[4][B_ * F_];                 // LN partial sums (T quarters)
__device__ float g_ss[4][B_ * F_];
__device__ uint4 g_WfragH[32 * 16 * 2 * 32];      // 512KB: [m16][kc32][kstep2][lane]
__device__ uint4 g_BfragH[(size_t)B_ * 4 * 16 * 512];  // 64MB: [b][ft][kc32][np][kstep2][lane]

// ---------------- helpers ----------------
DEV_INLINE uint32_t smem_u32(const void* p) {
    uint32_t a;
    asm("{ .reg .u64 t; cvta.to.shared.u64 t, %1; cvt.u32.u64 %0, t; }"
        : "=r"(a) : "l"(p));
    return a;
}

DEV_INLINE uint32_t h2pack(float a, float b) {
    __half2 h = __floats2half2_rn(a, b);
    return *reinterpret_cast<uint32_t*>(&h);
}

DEV_INLINE void cp_async16(uint32_t dst_smem, const void* src) {
    asm volatile(
        "{\n\t.reg .u64 g;\n\tcvta.to.global.u64 g, %1;\n\t"
        "cp.async.cg.shared.global [%0], [g], 16;\n\t}"
        :: "r"(dst_smem), "l"(src));
}
DEV_INLINE void cp_commit() { asm volatile("cp.async.commit_group;"); }
template <int N> DEV_INLINE void cp_wait() {
    asm volatile("cp.async.wait_group %0;" :: "n"(N));
}

// m16n8k16 fp16 mma, fp32 accumulate
DEV_INLINE void mma_f16(float* c, const uint32_t* a, uint32_t b0, uint32_t b1) {
    asm volatile(
        "mma.sync.aligned.m16n8k16.row.col.f32.f16.f16.f32 "
        "{%0,%1,%2,%3}, {%4,%5,%6,%7}, {%8,%9}, {%0,%1,%2,%3};"
        : "+f"(c[0]), "+f"(c[1]), "+f"(c[2]), "+f"(c[3])
        : "r"(a[0]), "r"(a[1]), "r"(a[2]), "r"(a[3]), "r"(b0), "r"(b1));
}

DEV_INLINE float gelu_exact(float v) {
    return 0.5f * v * (1.0f + erff(v * 0.70710678118654752f));
}

// ---------------- kernel 1: LN partial sums (1024 blks) + pack W (128 blks) --------
__global__ __launch_bounds__(256) void ln_and_packw_kernel(const float* __restrict__ x,
                                                           const float* __restrict__ W) {
    if (blockIdx.x < 1024) {                       // LN partial sums (T split in 4)
        const int tq = blockIdx.x & 3;
        const int fc = (blockIdx.x >> 2) & 1;
        const int b  = blockIdx.x >> 3;
        const int f  = fc * 256 + threadIdx.x;
        const float* xp = x + ((size_t)b * T_ + tq * 128) * F_ + f;
        float s = 0.f, ss = 0.f;
#pragma unroll 8
        for (int t = 0; t < 128; t++) {
            float v = xp[(size_t)t * F_];
            s += v;
            ss += v * v;
        }
        g_s[tq][b * F_ + f]  = s;
        g_ss[tq][b * F_ + f] = ss;
    } else {                                       // pack W -> fp16 A-frag order
        int lin = (blockIdx.x - 1024) * 256 + threadIdx.x;   // 32768 uint4s
        int lane = lin & 31;
        int kstep = (lin >> 5) & 1;
        int kc = (lin >> 6) & 15;
        int m16 = lin >> 10;
        int g = lane >> 2, tig = lane & 3;
        int mr = m16 * 16 + g;
        int tc = kc * 32 + kstep * 16 + 2 * tig;
        const float* w0 = W + (size_t)mr * T_ + tc;
        const float* w8 = W + (size_t)(mr + 8) * T_ + tc;
        uint4 v;
        v.x = h2pack(w0[0], w0[1]);
        v.y = h2pack(w8[0], w8[1]);
        v.z = h2pack(w0[8], w0[9]);
        v.w = h2pack(w8[8], w8[9]);
        g_WfragH[lin] = v;
    }
}

// ---------------- kernel 2: normalize + transpose into paired fp16 B-frag order ----
__global__ __launch_bounds__(256) void pack_xn_kernel(const float* __restrict__ x,
                                                      const float* __restrict__ gamma,
                                                      const float* __restrict__ beta) {
    __shared__ float s[32][132];
    __shared__ float s_mu[128], s_rs[128];
    const int kc = blockIdx.x, ft = blockIdx.y, b = blockIdx.z;
    const int tid = threadIdx.x;

    if (tid < 128) {
        int idx = b * F_ + ft * 128 + tid;
        float sm = g_s[0][idx] + g_s[1][idx] + g_s[2][idx] + g_s[3][idx];
        float sq = g_ss[0][idx] + g_ss[1][idx] + g_ss[2][idx] + g_ss[3][idx];
        float mean = sm * (1.0f / T_);
        float var = sq * (1.0f / T_) - mean * mean;
        s_mu[tid] = mean;
        s_rs[tid] = rsqrtf(fmaxf(var, 0.0f) + LN_EPS);
    }
    __syncthreads();

#pragma unroll
    for (int r = 0; r < 4; r++) {
        int i4 = tid + r * 256;
        int tl = i4 >> 5;
        int f4 = (i4 & 31) << 2;
        int gt = kc * 32 + tl;
        float4 v = *reinterpret_cast<const float4*>(
            x + ((size_t)b * T_ + gt) * F_ + ft * 128 + f4);
        float ga = gamma[gt], be = beta[gt];
        s[tl][f4 + 0] = (v.x - s_mu[f4 + 0]) * s_rs[f4 + 0] * ga + be;
        s[tl][f4 + 1] = (v.y - s_mu[f4 + 1]) * s_rs[f4 + 1] * ga + be;
        s[tl][f4 + 2] = (v.z - s_mu[f4 + 2]) * s_rs[f4 + 2] * ga + be;
        s[tl][f4 + 3] = (v.w - s_mu[f4 + 3]) * s_rs[f4 + 3] * ga + be;
    }
    __syncthreads();

    uint4* dst = g_BfragH + (((size_t)b * 4 + ft) * 16 + kc) * 512;
#pragma unroll
    for (int r = 0; r < 2; r++) {
        int o = tid + r * 256;                 // 512 uint4s
        int np = o >> 6;
        int rem = o & 63;
        int kstep = rem >> 5;
        int lane = rem & 31;
        int g = lane >> 2, tig = lane & 3;
        int t0 = kstep * 16 + 2 * tig;
        int f0 = np * 16 + g;
        uint4 v;
        v.x = h2pack(s[t0][f0],     s[t0 + 1][f0]);
        v.y = h2pack(s[t0 + 8][f0], s[t0 + 9][f0]);
        v.z = h2pack(s[t0][f0 + 8],     s[t0 + 1][f0 + 8]);
        v.w = h2pack(s[t0 + 8][f0 + 8], s[t0 + 9][f0 + 8]);
        dst[o] = v;
    }
}

// ---------------- kernel 3: fp16 GEMM, A via LDG (L2-hot), B via cp.async ----------
__global__ __launch_bounds__(THREADS, 2)
void timemix_gemm_kernel(const float* __restrict__ x,
                         const float* __restrict__ bvec,
                         float* __restrict__ out) {
    extern __shared__ char smem[];
    const int tid = threadIdx.x;
    const int wid = tid >> 5, lane = tid & 31;
    const int wm = wid & 3, wn = wid >> 2;          // 4 x 2 warps (32m x 64f)
    const int bm = blockIdx.x;                      // 0..3
    const int ft = blockIdx.y;                      // 0..3
    const int b = blockIdx.z;

    const uint32_t smem_base = smem_u32(smem);
    const uint4* Bsrc_base = g_BfragH + (((size_t)b * 4 + ft) * 16) * 512;
    // A frag address: (m16)*1024 + kc8*128 + ks*32 + lane  (uint4 units)
    const uint4* Abase = g_WfragH + (size_t)(bm * 8 + wm * 2) * 1024 + lane;

    auto load_stage = [&](int kc8) {
        uint32_t sB = smem_base + (kc8 % NSTAGE) * B_STAGE_B;
#pragma unroll
        for (int r = 0; r < 4; r++) {               // 1024 uint4s
            int i = tid + r * 256;
            int np = i >> 7;
            int rem = i & 127;
            int ks = rem >> 5;
            int ln = rem & 31;
            const uint4* src = Bsrc_base + (size_t)(2 * kc8 + (ks >> 1)) * 512
                               + np * 64 + (ks & 1) * 32 + ln;
            cp_async16(sB + i * 16, src);
        }
        cp_commit();
    };

    auto lda = [&](int kc8, int ks, uint32_t a[2][4]) {
#pragma unroll
        for (int i = 0; i < 2; i++) {
            uint4 v = __ldg(Abase + i * 1024 + kc8 * 128 + ks * 32);
            a[i][0] = v.x; a[i][1] = v.y; a[i][2] = v.z; a[i][3] = v.w;
        }
    };

    float acc[2][8][4];
#pragma unroll
    for (int i = 0; i < 2; i++)
#pragma unroll
        for (int j = 0; j < 8; j++)
#pragma unroll
            for (int r = 0; r < 4; r++) acc[i][j][r] = 0.0f;

    load_stage(0);
    load_stage(1);
    load_stage(2);

    uint32_t abuf[2][2][4];                         // ping-pong A frags
    lda(0, 0, abuf[0]);

    for (int kc = 0; kc < NKC; kc++) {
        if (kc < NKC - 2) cp_wait<2>();
        else if (kc == NKC - 2) cp_wait<1>();
        else cp_wait<0>();
        __syncthreads();

        const uint4* sB = reinterpret_cast<const uint4*>(
            smem + (kc % NSTAGE) * B_STAGE_B);

#pragma unroll
        for (int kstep = 0; kstep < 4; kstep++) {
            // prefetch next kstep's A from L2 (ping-pong)
            if (kstep < 3)          lda(kc, kstep + 1, abuf[(kstep + 1) & 1]);
            else if (kc + 1 < NKC)  lda(kc + 1, 0, abuf[0]);

            const uint32_t (*a)[4] = abuf[kstep & 1];
            uint4 bf[4];
#pragma unroll
            for (int jp = 0; jp < 4; jp++)
                bf[jp] = sB[((wn * 4 + jp) * 4 + kstep) * 32 + lane];
#pragma unroll
            for (int i = 0; i < 2; i++)
#pragma unroll
                for (int jp = 0; jp < 4; jp++) {
                    mma_f16(acc[i][2 * jp + 0], a[i], bf[jp].x, bf[jp].y);
                    mma_f16(acc[i][2 * jp + 1], a[i], bf[jp].z, bf[jp].w);
                }
        }

        if (kc + 3 < NKC) load_stage(kc + 3);   // writes stage (kc-1)%4, already consumed
    }

    // ---- epilogue: bias + exact GELU + residual ----
    const int g = lane >> 2, tig = lane & 3;
    const int m_warp = bm * 128 + wm * 32;
    const int f_warp = ft * 128 + wn * 64;
#pragma unroll
    for (int i = 0; i < 2; i++) {
#pragma unroll
        for (int h = 0; h < 2; h++) {
            int m = m_warp + i * 16 + g + 8 * h;
            float bv = bvec[m];
            const float* xr = x + ((size_t)b * M_ + m) * F_ + f_warp;
            float* yr = out + ((size_t)b * M_ + m) * F_ + f_warp;
#pragma unroll
            for (int j = 0; j < 8; j++) {
                int fo = j * 8 + tig * 2;
                float2 xv = *reinterpret_cast<const float2*>(xr + fo);
                float2 o;
                o.x = gelu_exact(acc[i][j][2 * h + 0] + bv) + xv.x;
                o.y = gelu_exact(acc[i][j][2 * h + 1] + bv) + xv.y;
                *reinterpret_cast<float2*>(yr + fo) = o;
            }
        }
    }
}

// ---------------- launch ----------------
extern "C" void kernel_launch(void* const* d_in, const int* in_sizes, int n_in,
                              void* d_out, int out_size) {
    const float* x     = (const float*)d_in[0];
    const float* gamma = (const float*)d_in[1];
    const float* beta  = (const float*)d_in[2];
    const float* W     = (const float*)d_in[3];
    const float* bvec  = (const float*)d_in[4];
    float* out = (float*)d_out;

    cudaFuncSetAttribute(timemix_gemm_kernel,
                         cudaFuncAttributeMaxDynamicSharedMemorySize, SMEM_BYTES);

    ln_and_packw_kernel<<<1024 + 128, 256>>>(x, W);
    {
        dim3 grid(16, F_ / 128, B_);
        pack_xn_kernel<<<grid, 256>>>(x, gamma, beta);
    }
    {
        dim3 grid(M_ / BM, F_ / BN, B_);   // (4, 4, 128)
        timemix_gemm_kernel<<<grid, THREADS, SMEM_BYTES>>>(x, bvec, out);
    }
}